// round 7
// baseline (speedup 1.0000x reference)
#include <cuda_runtime.h>

#define N_IN   2048
#define NN     512
#define BATCH  64

#define KSPLIT 64
#define KCHUNK (N_IN / KSPLIT)      // 32
#define BPER   8
#define BGROUPS (BATCH / BPER)      // 8

// scratch: partial drive sums, [KSPLIT][BATCH][NN] fp32 = 8 MB
__device__ float g_partial[(size_t)KSPLIT * BATCH * NN];

// ---------------------------------------------------------------------------
// Kernel 1: partial[ks][b][n] = sum_{k in chunk ks} x[b,k,n] * w[k,n]
// 128 threads/block, each thread owns 4 consecutive n (float4), BPER batches.
// x is streamed once (256 MB, the HBM roofline term); w re-used 8x per load.
// ---------------------------------------------------------------------------
__global__ __launch_bounds__(128)
void k_input_drive(const float* __restrict__ x, const float* __restrict__ w)
{
    const int n  = threadIdx.x * 4;           // 128 threads * 4 = 512 = NN
    const int ks = blockIdx.x;
    const int b0 = blockIdx.y * BPER;
    const int k0 = ks * KCHUNK;

    float4 acc[BPER];
#pragma unroll
    for (int i = 0; i < BPER; ++i) acc[i] = make_float4(0.f, 0.f, 0.f, 0.f);

    const float* wp = w + (size_t)k0 * NN + n;
    const float* xp = x + ((size_t)b0 * N_IN + k0) * NN + n;

#pragma unroll 4
    for (int k = 0; k < KCHUNK; ++k) {
        const float4 w4 = *(const float4*)(wp + (size_t)k * NN);
#pragma unroll
        for (int i = 0; i < BPER; ++i) {
            const float4 x4 = *(const float4*)(xp + ((size_t)i * N_IN + (size_t)k) * NN);
            acc[i].x = fmaf(x4.x, w4.x, acc[i].x);
            acc[i].y = fmaf(x4.y, w4.y, acc[i].y);
            acc[i].z = fmaf(x4.z, w4.z, acc[i].z);
            acc[i].w = fmaf(x4.w, w4.w, acc[i].w);
        }
    }

#pragma unroll
    for (int i = 0; i < BPER; ++i) {
        *(float4*)(g_partial + ((size_t)ks * BATCH + (b0 + i)) * NN + n) = acc[i];
    }
}

// ---------------------------------------------------------------------------
// Kernel 2: z_out_new, leave-one-out recurrent drive, partial reduction,
// state update, and all three outputs.
// grid = (NN/128, BATCH), 128 threads each (thread = one n).
// out layout: [v_new | z_new | z_out_new], each BATCH*NN fp32.
// ---------------------------------------------------------------------------
__global__ __launch_bounds__(128)
void k_update(const float* __restrict__ v,
              const float* __restrict__ z,
              const float* __restrict__ z_out,
              const float* __restrict__ w,
              float* __restrict__ out)
{
    __shared__ float s_zn[NN];

    const int b = blockIdx.y;
    const int n = blockIdx.x * 128 + threadIdx.x;

    const float ALPHA = (float)(1.0 - 0.05 / 10.0);  // 0.995
    const float BETA  = (float)(1.0 - 0.05 / 2.0);   // 0.975
    const float V_TH  = 2.0f;

    // z_out_new for this batch row into shared
    for (int i = threadIdx.x; i < NN; i += 128)
        s_zn[i] = BETA * z_out[(size_t)b * NN + i] + z[(size_t)b * NN + i];
    __syncthreads();

    // leave-one-out recurrent drive: sum_j z_out_new[b, j + (j>=n)] * w[N_IN+j, n]
    float acc = 0.f;
    const float* wr = w + (size_t)N_IN * NN + n;
#pragma unroll 4
    for (int j = 0; j < NN - 1; ++j) {
        const int m = j + (j >= n);
        acc = fmaf(s_zn[m], wr[(size_t)j * NN], acc);
    }

    // reduce k-split partials
    float drv = 0.f;
    const float* pp = g_partial + (size_t)b * NN + n;
#pragma unroll 8
    for (int s = 0; s < KSPLIT; ++s)
        drv += pp[(size_t)s * BATCH * NN];

    const float zb = z[(size_t)b * NN + n];
    const float vn = ALPHA * v[(size_t)b * NN + n] + drv + acc - V_TH * zb;

    out[(size_t)b * NN + n]                          = vn;                                  // v_new
    out[(size_t)BATCH * NN + (size_t)b * NN + n]     = (vn - V_TH > 0.f) ? 1.0f : 0.0f;     // z_new
    out[(size_t)2 * BATCH * NN + (size_t)b * NN + n] = s_zn[n];                             // z_out_new
}

extern "C" void kernel_launch(void* const* d_in, const int* in_sizes, int n_in,
                              void* d_out, int out_size)
{
    const float* x     = (const float*)d_in[0];
    const float* v     = (const float*)d_in[1];
    const float* z     = (const float*)d_in[2];
    const float* z_out = (const float*)d_in[3];
    const float* w     = (const float*)d_in[4];
    float* out = (float*)d_out;

    dim3 g1(KSPLIT, BGROUPS);
    k_input_drive<<<g1, 128>>>(x, w);

    dim3 g2(NN / 128, BATCH);
    k_update<<<g2, 128>>>(v, z, z_out, w, out);
}

// round 8
// speedup vs baseline: 1.8655x; 1.8655x over previous
#include <cuda_runtime.h>

#define N_IN   2048
#define NN     512
#define BATCH  64

#define KSPLIT 64
#define KCHUNK (N_IN / KSPLIT)      // 32
#define BPER   4
#define BGROUPS (BATCH / BPER)      // 16

#define JS 4                        // m-split groups in k_update
#define KPER_GROUP (KSPLIT / JS)    // 16 scratch partials per group

// scratch: partial drive sums, [KSPLIT][BATCH][NN] fp32 = 8 MB
__device__ float g_partial[(size_t)KSPLIT * BATCH * NN];

// ---------------------------------------------------------------------------
// Kernel 1: partial[ks][b][n] = sum_{k in chunk ks} x[b,k,n] * w[k,n]
// 1024 blocks x 128 threads; thread owns 4 consecutive n (float4), 4 batches.
// x streamed once (256 MB = the HBM roofline term); w is L2-resident (4 MB).
// ---------------------------------------------------------------------------
__global__ __launch_bounds__(128)
void k_input_drive(const float* __restrict__ x, const float* __restrict__ w)
{
    const int n  = threadIdx.x * 4;           // 128 threads * 4 = 512 = NN
    const int ks = blockIdx.x;
    const int b0 = blockIdx.y * BPER;
    const int k0 = ks * KCHUNK;

    float4 acc[BPER];
#pragma unroll
    for (int i = 0; i < BPER; ++i) acc[i] = make_float4(0.f, 0.f, 0.f, 0.f);

    const float* wp = w + (size_t)k0 * NN + n;
    const float* xp = x + ((size_t)b0 * N_IN + k0) * NN + n;

#pragma unroll 8
    for (int k = 0; k < KCHUNK; ++k) {
        const float4 w4 = *(const float4*)(wp + (size_t)k * NN);
#pragma unroll
        for (int i = 0; i < BPER; ++i) {
            const float4 x4 = *(const float4*)(xp + ((size_t)i * N_IN + (size_t)k) * NN);
            acc[i].x = fmaf(x4.x, w4.x, acc[i].x);
            acc[i].y = fmaf(x4.y, w4.y, acc[i].y);
            acc[i].z = fmaf(x4.z, w4.z, acc[i].z);
            acc[i].w = fmaf(x4.w, w4.w, acc[i].w);
        }
    }

#pragma unroll
    for (int i = 0; i < BPER; ++i) {
        *(float4*)(g_partial + ((size_t)ks * BATCH + (b0 + i)) * NN + n) = acc[i];
    }
}

// ---------------------------------------------------------------------------
// Kernel 2: z_out_new, LOO recurrent drive, k-split reduction, state update.
// grid = (NN/128, BATCH), 512 threads: 4 m-groups (ms) x 128 n-threads (nt).
// Each group: ~128 LOO iterations (4 independent accumulators) + 16 scratch
// partials; cross-group reduce in shared; ms==0 writes outputs.
// out layout: [v_new | z_new | z_out_new], each BATCH*NN fp32.
// ---------------------------------------------------------------------------
__global__ __launch_bounds__(512)
void k_update(const float* __restrict__ v,
              const float* __restrict__ z,
              const float* __restrict__ z_out,
              const float* __restrict__ w,
              float* __restrict__ out)
{
    __shared__ float s_zn[NN];
    __shared__ float s_part[JS][128];

    const int nt = threadIdx.x & 127;
    const int ms = threadIdx.x >> 7;          // 0..3
    const int b  = blockIdx.y;
    const int n  = blockIdx.x * 128 + nt;

    const float ALPHA = 0.995f;               // 1 - 0.05/10
    const float BETA  = 0.975f;               // 1 - 0.05/2
    const float V_TH  = 2.0f;

    // z_out_new for this batch row (512 threads -> one element each)
    s_zn[threadIdx.x] = BETA * z_out[(size_t)b * NN + threadIdx.x]
                             + z[(size_t)b * NN + threadIdx.x];
    __syncthreads();

    // leave-one-out recurrent drive, j-range per group
    const int jstart = ms * 128;
    const int jend   = (ms == JS - 1) ? (NN - 1) : (jstart + 128);

    const float* wr = w + (size_t)N_IN * NN + n;

    float a0 = 0.f, a1 = 0.f, a2 = 0.f, a3 = 0.f;
    int j = jstart;
#pragma unroll 2
    for (; j + 4 <= jend; j += 4) {
        const int m0 = j + 0 + (j + 0 >= n);
        const int m1 = j + 1 + (j + 1 >= n);
        const int m2 = j + 2 + (j + 2 >= n);
        const int m3 = j + 3 + (j + 3 >= n);
        a0 = fmaf(s_zn[m0], wr[(size_t)(j + 0) * NN], a0);
        a1 = fmaf(s_zn[m1], wr[(size_t)(j + 1) * NN], a1);
        a2 = fmaf(s_zn[m2], wr[(size_t)(j + 2) * NN], a2);
        a3 = fmaf(s_zn[m3], wr[(size_t)(j + 3) * NN], a3);
    }
    for (; j < jend; ++j) {
        const int m = j + (j >= n);
        a0 = fmaf(s_zn[m], wr[(size_t)j * NN], a0);
    }
    float acc = (a0 + a1) + (a2 + a3);

    // fold this group's share of the k-split scratch partials
    const float* pp = g_partial + ((size_t)ms * KPER_GROUP * BATCH + b) * NN + n;
#pragma unroll
    for (int s = 0; s < KPER_GROUP; ++s)
        acc += pp[(size_t)s * BATCH * NN];

    s_part[ms][nt] = acc;
    __syncthreads();

    if (ms == 0) {
        const float drv = (s_part[0][nt] + s_part[1][nt])
                        + (s_part[2][nt] + s_part[3][nt]);
        const float zb  = z[(size_t)b * NN + n];
        const float vn  = ALPHA * v[(size_t)b * NN + n] + drv - V_TH * zb;

        out[(size_t)b * NN + n]                          = vn;                              // v_new
        out[(size_t)BATCH * NN + (size_t)b * NN + n]     = (vn - V_TH > 0.f) ? 1.f : 0.f;   // z_new
        out[(size_t)2 * BATCH * NN + (size_t)b * NN + n] = s_zn[n];                         // z_out_new
    }
}

extern "C" void kernel_launch(void* const* d_in, const int* in_sizes, int n_in,
                              void* d_out, int out_size)
{
    const float* x     = (const float*)d_in[0];
    const float* v     = (const float*)d_in[1];
    const float* z     = (const float*)d_in[2];
    const float* z_out = (const float*)d_in[3];
    const float* w     = (const float*)d_in[4];
    float* out = (float*)d_out;

    dim3 g1(KSPLIT, BGROUPS);
    k_input_drive<<<g1, 128>>>(x, w);

    dim3 g2(NN / 128, BATCH);
    k_update<<<g2, 512>>>(v, z, z_out, w, out);
}

// round 14
// speedup vs baseline: 2.0617x; 1.1052x over previous
#include <cuda_runtime.h>

#define N_IN   2048
#define NN     512
#define BATCH  64

#define KSPLIT 64
#define KCHUNK (N_IN / KSPLIT)      // 32
#define BPER   4

#define ALPHA_C 0.995f              // 1 - 0.05/10
#define BETA_C  0.975f              // 1 - 0.05/2
#define VTH_C   2.0f

// scratch
__device__ float g_partial[(size_t)KSPLIT * BATCH * NN];  // 8 MB input-drive partials
__device__ float g_loo[(size_t)BATCH * NN];               // 128 KB recurrent partials

// ---------------------------------------------------------------------------
// Fused kernel: grid (16, 16, 2), 512 threads.
//  z == 0 : input drive. Block = 4 k-slices (tid>>7) x 128 n-threads (float4),
//           BPER batches. ks = bx*4+kq in [0,64). Streams x once (256 MB).
//  z == 1 : LOO recurrent drive. Block = (nchunk = bx&3, b = by*4 + bx>>2).
//           Computes z_out_new (written straight to out), LOO partial -> g_loo.
// LOO work overlaps the DRAM-bound drive inside one launch.
// ---------------------------------------------------------------------------
__global__ __launch_bounds__(512)
void k_fused(const float* __restrict__ x,
             const float* __restrict__ z,
             const float* __restrict__ z_out,
             const float* __restrict__ w,
             float* __restrict__ out)
{
    __shared__ float s_zn[NN];
    __shared__ float s_part[4][128];

    if (blockIdx.z == 0) {
        // ---------------- input drive ----------------
        const int nt = threadIdx.x & 127;
        const int kq = threadIdx.x >> 7;          // 0..3
        const int n  = nt * 4;
        const int ks = blockIdx.x * 4 + kq;       // 0..63
        const int b0 = blockIdx.y * BPER;
        const int k0 = ks * KCHUNK;

        float4 acc[BPER];
#pragma unroll
        for (int i = 0; i < BPER; ++i) acc[i] = make_float4(0.f, 0.f, 0.f, 0.f);

        const float* wp = w + (size_t)k0 * NN + n;
        const float* xp = x + ((size_t)b0 * N_IN + k0) * NN + n;

#pragma unroll 8
        for (int k = 0; k < KCHUNK; ++k) {
            const float4 w4 = *(const float4*)(wp + (size_t)k * NN);
#pragma unroll
            for (int i = 0; i < BPER; ++i) {
                const float4 x4 = *(const float4*)(xp + ((size_t)i * N_IN + (size_t)k) * NN);
                acc[i].x = fmaf(x4.x, w4.x, acc[i].x);
                acc[i].y = fmaf(x4.y, w4.y, acc[i].y);
                acc[i].z = fmaf(x4.z, w4.z, acc[i].z);
                acc[i].w = fmaf(x4.w, w4.w, acc[i].w);
            }
        }

#pragma unroll
        for (int i = 0; i < BPER; ++i) {
            *(float4*)(g_partial + ((size_t)ks * BATCH + (b0 + i)) * NN + n) = acc[i];
        }
    } else {
        // ---------------- LOO recurrent drive ----------------
        const int nt     = threadIdx.x & 127;
        const int ms     = threadIdx.x >> 7;      // 0..3 (j-range group)
        const int nchunk = blockIdx.x & 3;
        const int b      = blockIdx.y * 4 + (blockIdx.x >> 2);
        const int n      = nchunk * 128 + nt;

        // z_out_new for this batch row
        s_zn[threadIdx.x] = BETA_C * z_out[(size_t)b * NN + threadIdx.x]
                                   + z[(size_t)b * NN + threadIdx.x];
        __syncthreads();

        const int jstart = ms * 128;
        const int jend   = (ms == 3) ? (NN - 1) : (jstart + 128);

        const float* wr = w + (size_t)N_IN * NN + n;

        float a0 = 0.f, a1 = 0.f, a2 = 0.f, a3 = 0.f;
        int j = jstart;
#pragma unroll 2
        for (; j + 4 <= jend; j += 4) {
            const int m0 = j + 0 + (j + 0 >= n);
            const int m1 = j + 1 + (j + 1 >= n);
            const int m2 = j + 2 + (j + 2 >= n);
            const int m3 = j + 3 + (j + 3 >= n);
            a0 = fmaf(s_zn[m0], wr[(size_t)(j + 0) * NN], a0);
            a1 = fmaf(s_zn[m1], wr[(size_t)(j + 1) * NN], a1);
            a2 = fmaf(s_zn[m2], wr[(size_t)(j + 2) * NN], a2);
            a3 = fmaf(s_zn[m3], wr[(size_t)(j + 3) * NN], a3);
        }
        for (; j < jend; ++j) {
            const int m = j + (j >= n);
            a0 = fmaf(s_zn[m], wr[(size_t)j * NN], a0);
        }

        s_part[ms][nt] = (a0 + a1) + (a2 + a3);
        __syncthreads();

        if (ms == 0) {
            const float loo = (s_part[0][nt] + s_part[1][nt])
                            + (s_part[2][nt] + s_part[3][nt]);
            g_loo[(size_t)b * NN + n] = loo;
            out[(size_t)2 * BATCH * NN + (size_t)b * NN + n] = s_zn[n];   // z_out_new
        }
    }
}

// ---------------------------------------------------------------------------
// Combine: fold 64 k-split partials (L2-resident) + LOO partial, state update.
// grid = BATCH blocks x 512 threads (thread = one n).
// ---------------------------------------------------------------------------
__global__ __launch_bounds__(512)
void k_combine(const float* __restrict__ v,
               const float* __restrict__ z,
               float* __restrict__ out)
{
    const int b = blockIdx.x;
    const int n = threadIdx.x;

    const float* pp = g_partial + (size_t)b * NN + n;
    float a0 = 0.f, a1 = 0.f, a2 = 0.f, a3 = 0.f;
#pragma unroll
    for (int s = 0; s < KSPLIT; s += 4) {
        a0 += pp[(size_t)(s + 0) * BATCH * NN];
        a1 += pp[(size_t)(s + 1) * BATCH * NN];
        a2 += pp[(size_t)(s + 2) * BATCH * NN];
        a3 += pp[(size_t)(s + 3) * BATCH * NN];
    }
    const float drv = ((a0 + a1) + (a2 + a3)) + g_loo[(size_t)b * NN + n];

    const float zb = z[(size_t)b * NN + n];
    const float vn = ALPHA_C * v[(size_t)b * NN + n] + drv - VTH_C * zb;

    out[(size_t)b * NN + n]                      = vn;                               // v_new
    out[(size_t)BATCH * NN + (size_t)b * NN + n] = (vn - VTH_C > 0.f) ? 1.f : 0.f;   // z_new
}

extern "C" void kernel_launch(void* const* d_in, const int* in_sizes, int n_in,
                              void* d_out, int out_size)
{
    const float* x     = (const float*)d_in[0];
    const float* v     = (const float*)d_in[1];
    const float* z     = (const float*)d_in[2];
    const float* z_out = (const float*)d_in[3];
    const float* w     = (const float*)d_in[4];
    float* out = (float*)d_out;

    dim3 gf(16, 16, 2);
    k_fused<<<gf, 512>>>(x, z, z_out, w, out);

    k_combine<<<BATCH, 512>>>(v, z, out);
}